// round 4
// baseline (speedup 1.0000x reference)
#include <cuda_runtime.h>
#include <math.h>

typedef unsigned long long u64;

#define T_LEN   1000000
#define S_LEN    999999          // RK4 steps
#define LCH      31              // steps per chunk
#define NB1      128
#define BLK      256
#define C1       (NB1*BLK)       // 32768 chunks

// ---------------- dynamic smem layout (float offsets) ----------------
#define OFF_TO    0              // 7937 floats (BLK*LCH+1)
#define OFF_U     7940           // 384
#define OFF_SA    8324           // 720  (phaseB log tables; block0 reuses for level-2 logs)
#define OFF_SC    9044           // 720  (level-3 logs, block0)
#define OFF_GA    9764           // 384  (group aggregates, block0; sTsum during setup)
#define OFF_GP    10148          // 384
#define OFF_VC    10532          // 12
#define OFF_PT    10544          // 12
#define OFF_QT    10556          // 12
#define OFF_V     10568          // 12
#define OFF_M     10580          // 144 (col-major M)
#define OFF_STAGE 10724          // 8 warps * 3200 = 25600 (pool+fp64 scratch during setup)
#define SMEM_FLOATS (OFF_STAGE + 8*3200)     // 36324 floats = 145296 B

// ---------------- global scratch ----------------
__device__ float4 g_A [1024*3];      // warp aggregates
__device__ float4 g_E [1024*3];      // inclusive warp prefixes
__device__ float g_Mcol[144];
__device__ float g_ptv[12], g_qtv[12], g_vv[12];
__device__ float g_U[32*12];
__device__ float g_vc[12];
__device__ float g_TabAcol[32*144];  // M^(31*(j+1)), col-major
__device__ float g_TabBcol[32*144];  // M^(992*(j+1)), col-major
__device__ float g_SCcol[5*144];     // M^(31744*2^k), col-major

__device__ unsigned g_barArr = 0;
__device__ unsigned g_barGen = 0;

// product triples (dst,a,b) into pool, grouped in rounds (sources from earlier rounds)
__device__ const unsigned char tripD[99] = {
    2, 3,4, 5,6,7,8, 9,10,11,12,13,14,15,16,
    17,18,19,20,21,22,23,24,25,26,27,28,29,30,31,
    32, 33, 34,35, 36,37,38,39, 40,41,42,43,44,45,46,47,
    48,49,50,51,52,53,54,55,56,57,58,59,60,61,62,63,
    64, 65, 66,67, 68,69,70,71, 72,73,74,75,76,77,78,79,
    80,81,82,83,84,85,86,87,88,89,90,91,92,93,94,95,
    96, 97, 98, 99, 100 };
__device__ const unsigned char tripA[99] = {
    1, 2,2, 4,4,4,4, 8,8,8,8,8,8,8,8,
    16,16,16,16,16,16,16,16,16,16,16,16,16,16,16,
    31, 32, 33,33, 35,35,35,35, 39,39,39,39,39,39,39,39,
    47,47,47,47,47,47,47,47,47,47,47,47,47,47,47,47,
    63, 64, 65,65, 67,67,67,67, 71,71,71,71,71,71,71,71,
    79,79,79,79,79,79,79,79,79,79,79,79,79,79,79,79,
    95, 96, 97, 98, 99 };
__device__ const unsigned char tripB[99] = {
    1, 1,2, 1,2,3,4, 1,2,3,4,5,6,7,8,
    1,2,3,4,5,6,7,8,9,10,11,12,13,14,15,
    0, 32, 32,33, 32,33,34,35, 32,33,34,35,36,37,38,39,
    32,33,34,35,36,37,38,39,40,41,42,43,44,45,46,47,
    0, 64, 64,65, 64,65,66,67, 64,65,66,67,68,69,70,71,
    64,65,66,67,68,69,70,71,72,73,74,75,76,77,78,79,
    0, 96, 97, 98, 99 };
__device__ const short rndOff[23] = {0,1,3,7,15,30,31,32,34,38,46,62,63,64,66,70,78,94,95,96,97,98,99};

// ---------------- helpers ----------------
__device__ __forceinline__ void gridbar() {
    __threadfence();
    __syncthreads();
    if (threadIdx.x == 0) {
        unsigned gen = *((volatile unsigned*)&g_barGen);
        unsigned a = atomicAdd(&g_barArr, 1u);
        if (a == NB1 - 1u) {
            g_barArr = 0;
            __threadfence();
            *((volatile unsigned*)&g_barGen) = gen + 1u;
        } else {
            while (*((volatile unsigned*)&g_barGen) == gen) __nanosleep(64);
        }
        __threadfence();
    }
    __syncthreads();
}

__device__ __forceinline__ void ld12(float* s, const float4* p) {
    float4 a = p[0], b = p[1], c = p[2];
    s[0]=a.x; s[1]=a.y; s[2]=a.z; s[3]=a.w;
    s[4]=b.x; s[5]=b.y; s[6]=b.z; s[7]=b.w;
    s[8]=c.x; s[9]=c.y; s[10]=c.z; s[11]=c.w;
}
__device__ __forceinline__ void st12(float4* p, const float* s) {
    p[0] = make_float4(s[0],s[1],s[2],s[3]);
    p[1] = make_float4(s[4],s[5],s[6],s[7]);
    p[2] = make_float4(s[8],s[9],s[10],s[11]);
}
// s += Mcol * o (column-major matrix)
__device__ __forceinline__ void mv_acc(float* s, const float* M, const float* o) {
    #pragma unroll
    for (int j = 0; j < 12; j++) {
        float oj = o[j];
        #pragma unroll
        for (int r = 0; r < 12; r++) s[r] = fmaf(M[j*12+r], oj, s[r]);
    }
}
__device__ __forceinline__ void warpscan12(float* s, const float* sMat, int lane) {
    #pragma unroll
    for (int k = 0; k < 5; k++) {
        int d = 1 << k;
        float o[12];
        #pragma unroll
        for (int r = 0; r < 12; r++) o[r] = __shfl_up_sync(0xffffffffu, s[r], d);
        if (lane >= d) mv_acc(s, sMat + k*144, o);
    }
}

__device__ __forceinline__ u64 f2pack(float lo, float hi) {
    u64 r; asm("mov.b64 %0, {%1,%2};" : "=l"(r) : "f"(lo), "f"(hi)); return r;
}
__device__ __forceinline__ void f2unpack(float& lo, float& hi, u64 v) {
    asm("mov.b64 {%0,%1}, %2;" : "=f"(lo), "=f"(hi) : "l"(v));
}
__device__ __forceinline__ u64 ffma2(u64 a, u64 b, u64 c) {
    u64 d; asm("fma.rn.f32x2 %0, %1, %2, %3;" : "=l"(d) : "l"(a), "l"(b), "l"(c)); return d;
}

// ---------------- the fused kernel ----------------
__global__ void __launch_bounds__(BLK, 1) k_fused(
    const float* __restrict__ t_eval, const float* __restrict__ x0,
    const float* __restrict__ A,      const float* __restrict__ B,
    const float* __restrict__ Tout,   const float* __restrict__ loads_raw,
    const float* __restrict__ room_areas, float* __restrict__ outF)
{
    extern __shared__ float smemF[];
    float* sTo = smemF + OFF_TO;
    float* sU  = smemF + OFF_U;
    float* sSA = smemF + OFF_SA;
    float* sSC = smemF + OFF_SC;
    float* sGA = smemF + OFF_GA;
    float* sGP = smemF + OFF_GP;
    float* sVc = smemF + OFF_VC;
    float* sPt = smemF + OFF_PT;
    float* sQt = smemF + OFF_QT;
    float* sV  = smemF + OFF_V;
    float* sM  = smemF + OFF_M;
    float* sStage = smemF + OFF_STAGE;

    __shared__ double shQw[10], shb0[12], shBq[12], shh;
    __shared__ double sdpv[12], sdqv[12], sdvv[12];

    const int tid  = threadIdx.x;
    const int lane = tid & 31;
    const int warpSlot = tid >> 5;
    const int c = blockIdx.x * BLK + tid;     // chunk id
    const int wg = c >> 5;                    // global warp id

    // ---- phase 0: every block loads its Tout slab ----
    {
        int base = blockIdx.x * (BLK*LCH);
        for (int i = tid; i < BLK*LCH + 1; i += BLK) {
            int gi = base + i; if (gi > T_LEN-1) gi = T_LEN-1;
            sTo[i] = Tout[gi];
        }
    }

    // ---- setup: block 0 only ----
    if (blockIdx.x == 0) {
        float* sPool = sStage;                           // 101*144 = 14544 floats
        double* dS  = (double*)(sStage + 14560);         // fp64 scratch
        double* dA  = dS;        double* dA2 = dS + 144;
        double* dA3 = dS + 288;  double* dA4 = dS + 432;
        int t = tid;

        if (t == 0) shh = (double)t_eval[1] - (double)t_eval[0];
        if (t < 10) {
            double x = (double)loads_raw[10 + t];        // gain row (action = 0)
            shQw[t] = 1.0 / (1.0 + exp(-x)) * 50.0 * (double)room_areas[t];
        }
        if (t < 144) dA[t] = (double)A[t];
        __syncthreads();
        if (t < 12) {
            shb0[t] = (double)B[t*11];
            double s = 0.0;
            #pragma unroll
            for (int j = 0; j < 10; j++) s += (double)B[t*11 + 1 + j] * shQw[j];
            shBq[t] = s;
        }
        __syncthreads();
        if (t < 144) { int r=t/12,cc=t%12; double s=0;
            #pragma unroll
            for(int j=0;j<12;j++) s += dA[r*12+j]*dA[j*12+cc]; dA2[t]=s; }
        __syncthreads();
        if (t < 144) { int r=t/12,cc=t%12; double s=0;
            #pragma unroll
            for(int j=0;j<12;j++) s += dA2[r*12+j]*dA[j*12+cc]; dA3[t]=s; }
        __syncthreads();
        if (t < 144) { int r=t/12,cc=t%12; double s=0;
            #pragma unroll
            for(int j=0;j<12;j++) s += dA2[r*12+j]*dA2[j*12+cc]; dA4[t]=s; }
        __syncthreads();

        double h = shh, h2=h*h, h3=h2*h, h4=h3*h;
        if (t < 144) {
            int r=t/12, cc=t%12;
            double m = (r==cc?1.0:0.0) + h*dA[t] + h2/2.0*dA2[t] + h3/6.0*dA3[t] + h4/24.0*dA4[t];
            sPool[1*144 + t] = (float)m;
            sPool[0*144 + t] = (r==cc) ? 1.0f : 0.0f;
            g_Mcol[cc*12 + r] = (float)m;
        }
        if (t < 12) {
            int r = t;
            double ab0=0,a2b0=0,a3b0=0,abq=0,a2bq=0,a3bq=0;
            #pragma unroll
            for (int k = 0; k < 12; k++) {
                ab0 += dA [r*12+k]*shb0[k]; a2b0 += dA2[r*12+k]*shb0[k]; a3b0 += dA3[r*12+k]*shb0[k];
                abq += dA [r*12+k]*shBq[k]; a2bq += dA2[r*12+k]*shBq[k]; a3bq += dA3[r*12+k]*shBq[k];
            }
            double pt = h/2.0*shb0[r] + h2/3.0*ab0 + h3/8.0*a2b0 + h4/24.0*a3b0;
            double qt = h/2.0*shb0[r] + h2/6.0*ab0 + h3/24.0*a2b0;
            double vv = h*shBq[r] + h2/2.0*abq + h3/6.0*a2bq + h4/24.0*a3bq;
            sdpv[r]=pt; sdqv[r]=qt; sdvv[r]=vv;
            g_ptv[r]=(float)pt; g_qtv[r]=(float)qt; g_vv[r]=(float)vv;
        }
        __syncthreads();

        // power pool: per-round strided loops, one sync per round
        for (int rd = 0; rd < 22; rd++) {
            int s0 = rndOff[rd], s1 = rndOff[rd+1];
            int n = (s1 - s0) * 144;
            for (int idx = t; idx < n; idx += BLK) {
                int k = s0 + idx / 144, e = idx % 144;
                const float* a = sPool + tripA[k]*144;
                const float* b = sPool + tripB[k]*144;
                int r = e/12, cc = e%12;
                float acc = 0.f;
                #pragma unroll
                for (int j = 0; j < 12; j++) acc = fmaf(a[r*12+j], b[j*12+cc], acc);
                sPool[tripD[k]*144 + e] = acc;
            }
            __syncthreads();
        }

        // conv coefficients
        for (int idx = t; idx < 384; idx += BLK) {
            int i = idx / 12, r = idx % 12;
            double s = 0.0;
            if (i <= 30) {
                const float* m = sPool + (30 - i)*144;
                #pragma unroll
                for (int j = 0; j < 12; j++) s += (double)m[r*12+j] * sdpv[j];
            }
            if (i >= 1) {
                const float* m = sPool + (31 - i)*144;
                #pragma unroll
                for (int j = 0; j < 12; j++) s += (double)m[r*12+j] * sdqv[j];
            }
            g_U[i*12 + r] = (float)s;
        }
        if (t < 144) {                            // sum of M^0..M^30 (into sGA scratch)
            float s = 0.f;
            for (int j = 0; j <= 30; j++) s += sPool[j*144 + t];
            sGA[t] = s;
        }
        __syncthreads();
        if (t < 12) {
            double s = 0.0;
            #pragma unroll
            for (int k = 0; k < 12; k++) s += (double)sGA[t*12 + k] * sdvv[k];
            g_vc[t] = (float)s;
        }
        // exports col-major
        for (int idx = t; idx < 32*144; idx += BLK) {
            int j = idx / 144, e = idx % 144, r = e/12, cc = e%12;
            g_TabAcol[j*144 + cc*12 + r] = sPool[(32 + j)*144 + e];
            g_TabBcol[j*144 + cc*12 + r] = sPool[(64 + j)*144 + e];
        }
        for (int idx = t; idx < 5*144; idx += BLK) {
            int j = idx / 144, e = idx % 144, r = e/12, cc = e%12;
            g_SCcol[j*144 + cc*12 + r] = sPool[(96 + j)*144 + e];
        }
    }

    gridbar();   // barrier 1: setup done

    // ---- phaseB: load tables, conv forcing prefix + warp scan ----
    for (int i = tid; i < 384; i += BLK) sU[i] = g_U[i];
    for (int i = tid; i < 5*144; i += BLK) {
        int k = i / 144, e = i % 144;
        sSA[i] = g_TabAcol[((1<<k) - 1)*144 + e];
    }
    if (tid < 12) {
        sVc[tid] = g_vc[tid];
        sPt[tid] = g_ptv[tid];
        sQt[tid] = g_qtv[tid];
        sV [tid] = g_vv[tid];
    }
    for (int i = tid; i < 144; i += BLK) sM[i] = g_Mcol[i];
    __syncthreads();

    float s[12];
    #pragma unroll
    for (int r = 0; r < 12; r++) s[r] = sVc[r];
    const int off = tid * LCH;
    #pragma unroll
    for (int i = 0; i < 32; i++) {
        float to = sTo[off + i];
        #pragma unroll
        for (int r = 0; r < 12; r++) s[r] = fmaf(sU[i*12+r], to, s[r]);
    }
    if (c == 0) {                 // fold M^31 * x0 into chunk 0
        float xv[12];
        #pragma unroll
        for (int r = 0; r < 12; r++) xv[r] = x0[r];
        mv_acc(s, sSA, xv);
    }
    warpscan12(s, sSA, lane);
    if (lane == 31) st12(&g_A[wg*3], s);

    gridbar();   // barrier 2: all warp aggregates in g_A

    // ---- level 2+3 scan (block 0 only): E[w] for 1024 warps ----
    if (blockIdx.x == 0) {
        // load level-2 logs into sSA (reuse) and level-3 logs into sSC
        for (int i = tid; i < 5*144; i += BLK) {
            int k = i / 144, e = i % 144;
            sSA[i] = g_TabBcol[((1<<k) - 1)*144 + e];
            sSC[i] = g_SCcol[i];
        }
        __syncthreads();
        float p[4][12];
        #pragma unroll
        for (int it = 0; it < 4; it++) {
            int g = warpSlot*4 + it;
            ld12(p[it], &g_A[(g*32 + lane)*3]);
            warpscan12(p[it], sSA, lane);
            if (lane == 31) {
                #pragma unroll
                for (int r = 0; r < 12; r++) sGA[g*12+r] = p[it][r];
            }
        }
        __syncthreads();
        if (warpSlot == 0) {
            float s2[12];
            #pragma unroll
            for (int r = 0; r < 12; r++) s2[r] = sGA[lane*12+r];
            warpscan12(s2, sSC, lane);
            #pragma unroll
            for (int r = 0; r < 12; r++) sGP[lane*12+r] = s2[r];
        }
        __syncthreads();
        #pragma unroll
        for (int it = 0; it < 4; it++) {
            int g = warpSlot*4 + it;
            if (g >= 1) {
                float gp[12];
                #pragma unroll
                for (int r = 0; r < 12; r++) gp[r] = sGP[(g-1)*12+r];
                mv_acc(p[it], g_TabBcol + lane*144, gp);
            }
            st12(&g_E[(g*32 + lane)*3], p[it]);
        }
    }

    gridbar();   // barrier 3: E ready

    // ---- phaseD: reconstruct start state, step 31 times, staged stores ----
    float pw[12];
    #pragma unroll
    for (int r = 0; r < 12; r++) pw[r] = __shfl_up_sync(0xffffffffu, s[r], 1);

    float st[12];
    if (c == 0) {
        #pragma unroll
        for (int r = 0; r < 12; r++) st[r] = x0[r];
        float4* o4 = (float4*)outF;
        o4[0] = make_float4(st[0],st[1],st[2],st[3]);
        o4[1] = make_float4(st[4],st[5],st[6],st[7]);
        o4[2] = make_float4(st[8],st[9],st[10],st[11]);
    } else {
        float Ev[12];
        bool haveE = (wg >= 1);
        if (haveE) ld12(Ev, &g_E[(wg-1)*3]);
        if (lane == 0) {
            #pragma unroll
            for (int r = 0; r < 12; r++) st[r] = Ev[r];
        } else {
            #pragma unroll
            for (int r = 0; r < 12; r++) st[r] = pw[r];
            if (haveE) mv_acc(st, g_TabAcol + (lane-1)*144, Ev);
        }
    }

    // packed state + register-resident matrix
    u64 S[6];
    #pragma unroll
    for (int p2 = 0; p2 < 6; p2++) S[p2] = f2pack(st[2*p2], st[2*p2+1]);
    u64 Mr[72];
    #pragma unroll
    for (int i = 0; i < 72; i++) Mr[i] = ((const u64*)sM)[i];
    const u64* Pt2 = (const u64*)sPt;
    const u64* Qt2 = (const u64*)sQt;
    const u64* V2  = (const u64*)sV;

    float* row = sStage + warpSlot*3200 + lane*100;
    const float* wbase = sStage + warpSlot*3200;
    const int cBase = blockIdx.x*BLK + warpSlot*32;

    float tot = sTo[off];
    #pragma unroll 1
    for (int tile = 0; tile < 4; tile++) {
        const int i0 = tile * 8;
        #pragma unroll
        for (int i = 0; i < 8; i++) {
            if (i0 + i < LCH) {
                float ton = sTo[off + i0 + i + 1];
                u64 tot2 = f2pack(tot, tot), ton2 = f2pack(ton, ton);
                u64 NS[6];
                #pragma unroll
                for (int p2 = 0; p2 < 6; p2++)
                    NS[p2] = ffma2(Pt2[p2], tot2, ffma2(Qt2[p2], ton2, V2[p2]));
                #pragma unroll
                for (int jp = 0; jp < 6; jp++) {
                    float xa, xb; f2unpack(xa, xb, S[jp]);
                    u64 xa2 = f2pack(xa, xa), xb2 = f2pack(xb, xb);
                    #pragma unroll
                    for (int p2 = 0; p2 < 6; p2++) NS[p2] = ffma2(Mr[(2*jp)*6+p2],   xa2, NS[p2]);
                    #pragma unroll
                    for (int p2 = 0; p2 < 6; p2++) NS[p2] = ffma2(Mr[(2*jp+1)*6+p2], xb2, NS[p2]);
                }
                #pragma unroll
                for (int p2 = 0; p2 < 6; p2++) S[p2] = NS[p2];
                tot = ton;
                float* dst = row + i*12;
                ulonglong2 v0; v0.x = S[0]; v0.y = S[1];
                ulonglong2 v1; v1.x = S[2]; v1.y = S[3];
                ulonglong2 v2; v2.x = S[4]; v2.y = S[5];
                ((ulonglong2*)dst)[0] = v0;
                *(ulonglong2*)(dst + 4) = v1;
                *(ulonglong2*)(dst + 8) = v2;
            }
        }
        __syncwarp();
        // flush: 32 segments x 24 16B-units, coalesced-ish
        #pragma unroll 1
        for (int f = lane; f < 768; f += 32) {
            int seg = f / 24;
            int w16 = f - seg*24;
            int istep = w16 / 3;
            if (i0 + istep < LCH) {
                long n1 = (long)(cBase + seg)*LCH + i0 + istep + 1;
                if (n1 <= (long)S_LEN) {
                    ulonglong2 v = *(const ulonglong2*)(wbase + seg*100 + w16*4);
                    *(ulonglong2*)(outF + n1*12 + (w16 - istep*3)*4) = v;
                }
            }
        }
        __syncwarp();
    }
}

// ---------------- launch ----------------
extern "C" void kernel_launch(void* const* d_in, const int* in_sizes, int n_in,
                              void* d_out, int out_size) {
    const float* t_eval = (const float*)d_in[0];
    const float* x0     = (const float*)d_in[1];
    const float* A      = (const float*)d_in[2];
    const float* B      = (const float*)d_in[3];
    const float* Tout   = (const float*)d_in[4];
    const float* loads  = (const float*)d_in[5];
    const float* areas  = (const float*)d_in[6];
    float* outF = (float*)d_out;

    size_t smemB = (size_t)SMEM_FLOATS * sizeof(float);
    cudaFuncSetAttribute(k_fused, cudaFuncAttributeMaxDynamicSharedMemorySize, (int)smemB);
    k_fused<<<NB1, BLK, smemB>>>(t_eval, x0, A, B, Tout, loads, areas, outF);
}